// round 10
// baseline (speedup 1.0000x reference)
#include <cuda_runtime.h>
#include <math.h>

#define BATCH 256
#define TT    257
#define HID   512
#define EMB   256
#define CF    512
#define HW    64
#define NMIX  20
#define KPM   1056            // gates K padded: 1029 -> 33 tiles of 32
#define OUTROWS (BATCH*TT)    // 65792
#define OFF   (OUTROWS*NMIX)  // 1315840

// ---------------- device scratch (no allocs allowed) ----------------
__device__ float g_WgT [KPM*2048];     // gates weights, K-major, tf32, cols j'=unit*4+gate (8.7 MB)
__device__ float g_bias2[2048];        // bih+bhh in j' order
__device__ float g_WkT [4608*256];     // conv weights, K-major   (4.7 MB)
__device__ float g_WchT[512*256];      // W_conv_h transposed
__device__ float g_WpT [512*128];      // W_fc_params transposed (padded to 128)
__device__ float g_orgT[BATCH*HW*CF];  // backbone transposed to [b][hw][c] (33.5 MB)
__device__ float g_xem [BATCH*HW*EMB]; // conv output [b][hw][e]  (16.8 MB)
__device__ float g_gem [BATCH*EMB];    // per-step g_em
__device__ float g_hbuf[2][BATCH*HID];
__device__ float g_c   [BATCH*HID];
__device__ float g_att [BATCH*CF];

__device__ __forceinline__ float sigm(float x) { return 1.f / (1.f + expf(-x)); }
__device__ __forceinline__ float ftanh(float x) {
    float y; asm("tanh.approx.f32 %0, %1;" : "=f"(y) : "f"(x)); return y;
}
__device__ __forceinline__ float to_tf32(float v) {
    unsigned u; asm("cvt.rna.tf32.f32 %0, %1;" : "=r"(u) : "f"(v));
    return __uint_as_float(u);
}

// ---------------- one-time pack / transpose ----------------
__global__ void pack_kernel(const float* __restrict__ Wih, const float* __restrict__ Whh,
                            const float* __restrict__ Wch, const float* __restrict__ Wp,
                            const float* __restrict__ Kc,  const float* __restrict__ bb,
                            const float* __restrict__ bih, const float* __restrict__ bhh)
{
    int i = blockIdx.x * 256 + threadIdx.x;
    if (i < KPM*2048) {                      // WgT[k][j'], j' = unit*4 + gate, tf32-rounded
        int k = i / 2048, jp = i - k*2048;
        int u = jp >> 2, g = jp & 3;
        int j = g*512 + u;
        float v = 0.f;
        if (k < 517)       v = Wih[j*517 + k];
        else if (k < 1029) v = Whh[j*512 + (k-517)];
        g_WgT[i] = to_tf32(v);
    }
    if (i < 2048) {                          // combined bias in j' order
        int u = i >> 2, g = i & 3;
        int j = g*512 + u;
        g_bias2[i] = bih[j] + bhh[j];
    }
    if (i < 4608*256) {                      // WkT[c*9+tap][e]
        int k = i >> 8, e = i & 255;
        int c = k / 9, tap = k - c*9;
        g_WkT[i] = Kc[(e*512 + c)*9 + tap];
    }
    if (i < 512*256) {                       // WchT[k][e]
        int k = i >> 8, e = i & 255;
        g_WchT[i] = Wch[e*512 + k];
    }
    if (i < 512*128) {                       // WpT[k][j]
        int k = i >> 7, j = i & 127;
        g_WpT[i] = (j < 123) ? Wp[j*512 + k] : 0.f;
    }
    if (i < BATCH*HW*CF) {                   // orgT[b][hw][c]
        int c = i & 511; int hw = (i >> 9) & 63; int b = i >> 15;
        g_orgT[i] = bb[(b*CF + c)*HW + hw];
    }
}

// ---------------- h0/c0 = tanh(z @ W_fc_hc^T + b) ----------------
__global__ void init_hc_kernel(const float* __restrict__ z, const float* __restrict__ Whc,
                               const float* __restrict__ bhc)
{
    __shared__ float sh_z[4*128];
    int tid = threadIdx.x;                   // 256
    int b0 = blockIdx.x * 4;
    for (int i = tid; i < 512; i += 256) sh_z[i] = z[b0*128 + i];
    __syncthreads();
    for (int jj = tid; jj < 1024; jj += 256) {
        float a0 = 0.f, a1 = 0.f, a2 = 0.f, a3 = 0.f;
        for (int k = 0; k < 128; k++) {
            float w = Whc[jj*128 + k];
            a0 += w * sh_z[k];       a1 += w * sh_z[128 + k];
            a2 += w * sh_z[256 + k]; a3 += w * sh_z[384 + k];
        }
        float bv = bhc[jj];
        float v[4] = { tanhf(a0+bv), tanhf(a1+bv), tanhf(a2+bv), tanhf(a3+bv) };
        #pragma unroll
        for (int b = 0; b < 4; b++) {
            if (jj < 512) g_hbuf[0][(b0+b)*512 + jj]      = v[b];
            else          g_c     [(b0+b)*512 + (jj-512)] = v[b];
        }
    }
}

// ---------------- conv3x3 SAME as implicit GEMM: xem[m][e], M=B*HW, K=4608 ----------------
__global__ void conv_kernel(const float* __restrict__ bb, const float* __restrict__ bconv)
{
    __shared__ float As[16*68];
    __shared__ float Bs[16*64];
    int tid = threadIdx.x;
    int m0 = blockIdx.x * 64;
    int n0 = blockIdx.y * 64;
    int tx = tid & 15, ty = tid >> 4;
    float acc[4][4] = {};

    int lmm = tid & 63, lkb = tid >> 6;      // loader roles
    int m = m0 + lmm;
    int bidx = m >> 6, pix = m & 63, py = pix >> 3, px = pix & 7;

    for (int kt = 0; kt < 4608; kt += 16) {
        #pragma unroll
        for (int i = 0; i < 4; i++) {        // A tile (patches)
            int kk = lkb*4 + i; int k = kt + kk;
            int c = k / 9, tap = k - c*9;
            int dy = tap / 3, dx = tap - dy*3;
            int yy = py + dy - 1, xx = px + dx - 1;
            float v = 0.f;
            if (yy >= 0 && yy < 8 && xx >= 0 && xx < 8)
                v = bb[((bidx*CF + c) << 6) + yy*8 + xx];
            As[kk*68 + lmm] = v;
        }
        #pragma unroll
        for (int i = 0; i < 4; i++) {        // B tile (weights, coalesced)
            int kk = lkb*4 + i;
            Bs[kk*64 + lmm] = g_WkT[(kt+kk)*256 + n0 + lmm];
        }
        __syncthreads();
        #pragma unroll
        for (int kk = 0; kk < 16; kk++) {
            float4 a  = *(const float4*)&As[kk*68 + ty*4];
            float4 bv = *(const float4*)&Bs[kk*64 + tx*4];
            acc[0][0] += a.x*bv.x; acc[0][1] += a.x*bv.y; acc[0][2] += a.x*bv.z; acc[0][3] += a.x*bv.w;
            acc[1][0] += a.y*bv.x; acc[1][1] += a.y*bv.y; acc[1][2] += a.y*bv.z; acc[1][3] += a.y*bv.w;
            acc[2][0] += a.z*bv.x; acc[2][1] += a.z*bv.y; acc[2][2] += a.z*bv.z; acc[2][3] += a.z*bv.w;
            acc[3][0] += a.w*bv.x; acc[3][1] += a.w*bv.y; acc[3][2] += a.w*bv.z; acc[3][3] += a.w*bv.w;
        }
        __syncthreads();
    }
    int e0 = n0 + tx*4;
    float b0v = bconv[e0], b1v = bconv[e0+1], b2v = bconv[e0+2], b3v = bconv[e0+3];
    #pragma unroll
    for (int r = 0; r < 4; r++) {
        int mm = m0 + ty*4 + r;
        float4 o;
        o.x = acc[r][0] + b0v; o.y = acc[r][1] + b1v;
        o.z = acc[r][2] + b2v; o.w = acc[r][3] + b3v;
        *(float4*)&g_xem[mm*256 + e0] = o;
    }
}

// ---------------- gem device helper: g_em = h @ WchT + b (16 batches x 32 cols / block) ----
__device__ __forceinline__ void gem_block(const float* __restrict__ hsrc,
                                          const float* __restrict__ bconvh,
                                          float* sh_h, int bid, int tid)
{
    int bg = (bid >> 3) * 16;
    int cg = (bid & 7) * 32;

    for (int i = tid; i < 16*512; i += 256) sh_h[i] = hsrc[bg*512 + i];
    __syncthreads();

    int wid = tid >> 5, lane = tid & 31;
    int col = cg + lane;
    const float* h0 = &sh_h[(wid*2)*512];
    const float* h1 = &sh_h[(wid*2+1)*512];
    float a0 = 0.f, a1 = 0.f;
    #pragma unroll 8
    for (int k = 0; k < 512; k++) {
        float w = g_WchT[k*256 + col];
        a0 += w * h0[k];
        a1 += w * h1[k];
    }
    float bv = bconvh[col];
    g_gem[(bg + wid*2    )*256 + col] = a0 + bv;
    g_gem[(bg + wid*2 + 1)*256 + col] = a1 + bv;
}

// ---------------- pre-loop gem for t=0 ----------------
__global__ void gem0_kernel(const float* __restrict__ bconvh)
{
    __shared__ float sh_h[16*512];
    gem_block(g_hbuf[0], bconvh, sh_h, blockIdx.x, threadIdx.x);
}

// ---------------- per-step: tanh attention + softmax + att reduce (1 batch / block) -------
__global__ void attn_kernel(const float* __restrict__ watt, const float* __restrict__ batt,
                            int t)
{
    __shared__ float sh_gem[256];
    __shared__ float sh_w[256];
    __shared__ float sh_sc[64];
    int tid = threadIdx.x;                   // 256
    int b = blockIdx.x;

    sh_gem[tid] = g_gem[b*256 + tid];
    sh_w[tid]   = watt[tid];
    __syncthreads();

    int wid = tid >> 5, lane = tid & 31;
    float bav = batt[0];
    const float4* gem4 = (const float4*)sh_gem;
    const float4* w4   = (const float4*)sh_w;
    float4 gA = gem4[2*lane], gB = gem4[2*lane+1];
    float4 wA = w4[2*lane],   wB = w4[2*lane+1];

    #pragma unroll
    for (int hw = wid; hw < 64; hw += 8) {   // scores
        const float4* xr = (const float4*)&g_xem[(b*64 + hw)*256];
        float4 x0 = xr[2*lane], x1 = xr[2*lane+1];
        float s;
        s  = wA.x * ftanh(x0.x + gA.x);
        s += wA.y * ftanh(x0.y + gA.y);
        s += wA.z * ftanh(x0.z + gA.z);
        s += wA.w * ftanh(x0.w + gA.w);
        s += wB.x * ftanh(x1.x + gB.x);
        s += wB.y * ftanh(x1.y + gB.y);
        s += wB.z * ftanh(x1.z + gB.z);
        s += wB.w * ftanh(x1.w + gB.w);
        #pragma unroll
        for (int o = 16; o; o >>= 1) s += __shfl_xor_sync(0xffffffffu, s, o);
        if (lane == 0) sh_sc[hw] = s + bav;
    }
    __syncthreads();

    if (wid == 0) {                          // softmax over 64
        float v0 = sh_sc[lane], v1 = sh_sc[32 + lane];
        float m = fmaxf(v0, v1);
        #pragma unroll
        for (int o = 16; o; o >>= 1) m = fmaxf(m, __shfl_xor_sync(0xffffffffu, m, o));
        float e0 = expf(v0 - m), e1 = expf(v1 - m);
        float s = e0 + e1;
        #pragma unroll
        for (int o = 16; o; o >>= 1) s += __shfl_xor_sync(0xffffffffu, s, o);
        float inv = 1.f / s;
        sh_sc[lane] = e0*inv; sh_sc[32 + lane] = e1*inv;
    }
    __syncthreads();

    {                                        // att = alpha @ orgfeat  (2 cols / thread)
        const float* org = &g_orgT[b*64*512];
        float a0 = 0.f, a1 = 0.f;
        #pragma unroll 8
        for (int hw = 0; hw < 64; hw++) {
            float al = sh_sc[hw];
            a0 += al * org[hw*512 + tid];
            a1 += al * org[hw*512 + 256 + tid];
        }
        g_att[b*512 + tid]       = a0;
        g_att[b*512 + 256 + tid] = a1;
    }
}

// ---------------- per-step: gates GEMM via tf32 mma.sync + fused LSTM cell ----------------
// Block tile 64(M) x 64(N), K-tile 32. 8 warps = 4(M) x 2(N); warp = m16 x n32.
// Columns are j' = unit*4 + gate; lane pairs (lane, lane^1) own all 4 gates of one unit.
__global__ void gates_kernel(const float* __restrict__ sketch, int t)
{
    __shared__ float As[64*36];              // [m][k], stride 36 -> conflict-free frags
    __shared__ float Bs[32*72];              // [k][n], stride 72 -> conflict-free frags
    int tid = threadIdx.x;                   // 256
    int m0 = blockIdx.x * 64;
    int n0 = blockIdx.y * 64;
    const float* hcur  = g_hbuf[t & 1];
    float*       hnext = g_hbuf[(t + 1) & 1];
    int wid = tid >> 5, lane = tid & 31;
    int wm = (wid & 3) * 16, wn = (wid >> 2) * 32;
    int lq = lane >> 2, lr = lane & 3;
    float acc[4][4] = {};

    for (int kt = 0; kt < KPM; kt += 32) {
        #pragma unroll
        for (int j = 0; j < 8; j++) {        // A tile 64x32: concat(att, pt, h), tf32
            int idx = j*256 + tid;
            int m = idx >> 5, k2 = idx & 31;
            int k = kt + k2;
            int row = m0 + m;
            float v;
            if (k < 512)       v = g_att[row*512 + k];
            else if (k < 517)  { int kp = k - 512;
                                 v = (t == 0) ? (kp == 2 ? 1.f : 0.f)
                                              : sketch[((t-1)*BATCH + row)*5 + kp]; }
            else if (k < 1029) v = hcur[row*512 + (k - 517)];
            else               v = 0.f;
            As[m*36 + k2] = to_tf32(v);
        }
        #pragma unroll
        for (int j = 0; j < 8; j++) {        // B tile 32x64 (already tf32)
            int idx = j*256 + tid;
            int k2 = idx >> 6, n = idx & 63;
            Bs[k2*72 + n] = g_WgT[(kt + k2)*2048 + n0 + n];
        }
        __syncthreads();
        #pragma unroll
        for (int kf = 0; kf < 4; kf++) {
            int kb = kf*8;
            unsigned a0 = __float_as_uint(As[(wm + lq    )*36 + kb + lr    ]);
            unsigned a1 = __float_as_uint(As[(wm + lq + 8)*36 + kb + lr    ]);
            unsigned a2 = __float_as_uint(As[(wm + lq    )*36 + kb + lr + 4]);
            unsigned a3 = __float_as_uint(As[(wm + lq + 8)*36 + kb + lr + 4]);
            #pragma unroll
            for (int nf = 0; nf < 4; nf++) {
                unsigned b0 = __float_as_uint(Bs[(kb + lr    )*72 + wn + nf*8 + lq]);
                unsigned b1 = __float_as_uint(Bs[(kb + lr + 4)*72 + wn + nf*8 + lq]);
                asm volatile(
                    "mma.sync.aligned.m16n8k8.row.col.f32.tf32.tf32.f32 "
                    "{%0,%1,%2,%3}, {%4,%5,%6,%7}, {%8,%9}, {%0,%1,%2,%3};"
                    : "+f"(acc[nf][0]), "+f"(acc[nf][1]),
                      "+f"(acc[nf][2]), "+f"(acc[nf][3])
                    : "r"(a0), "r"(a1), "r"(a2), "r"(a3), "r"(b0), "r"(b1));
            }
        }
        __syncthreads();
    }

    // Epilogue: lane pair exchange -> each lane has (i,f,g,o) for one (row, unit)
    int r0 = m0 + wm + lq;
    bool ev = (lane & 1) == 0;
    #pragma unroll
    for (int nf = 0; nf < 4; nf++) {
        float p0 = __shfl_xor_sync(0xffffffffu, acc[nf][0], 1);
        float p1 = __shfl_xor_sync(0xffffffffu, acc[nf][1], 1);
        float p2 = __shfl_xor_sync(0xffffffffu, acc[nf][2], 1);
        float p3 = __shfl_xor_sync(0xffffffffu, acc[nf][3], 1);
        int u = (n0 + wn + nf*8) >> 2; u += (lr >> 1);
        int row = ev ? r0 : (r0 + 8);
        float iv, fv, gv, ov;
        if (ev) { iv = acc[nf][0]; fv = acc[nf][1]; gv = p0;         ov = p1;         }
        else    { iv = p2;         fv = p3;         gv = acc[nf][2]; ov = acc[nf][3]; }
        float4 bz = *(const float4*)&g_bias2[u*4];
        iv += bz.x; fv += bz.y; gv += bz.z; ov += bz.w;
        float co = g_c[row*512 + u];
        float cn = sigm(fv)*co + sigm(iv)*tanhf(gv);
        float hn = sigm(ov)*tanhf(cn);
        g_c[row*512 + u]   = cn;
        hnext[row*512 + u] = hn;
    }
}

// ---------------- per-step fused: head(t) [blocks 128..255] + gem(t+1) [blocks 0..127] ----
// Both read hbuf[(t+1)&1], written by gates(t). Independent outputs.
__global__ void head_gem_kernel(const float* __restrict__ bfc, float* __restrict__ out,
                                const float* __restrict__ bconvh, int t)
{
    __shared__ float sh_h[16*512];           // gem branch (32 KB)
    __shared__ float sh_h2[2*512];           // head branch
    __shared__ float sh_y[2*128];
    __shared__ float sh_mx[2], sh_inv[2];
    int tid = threadIdx.x;                   // 256
    const float* hn = g_hbuf[(t + 1) & 1];

    if (blockIdx.x < 128) {                  // ---- gem for step t+1 ----
        gem_block(hn, bconvh, sh_h, blockIdx.x, tid);
        return;
    }

    // ---- head for 2 batches ----
    int bs = tid >> 7;                       // batch slot 0/1
    int lt = tid & 127;
    int b = (blockIdx.x - 128)*2 + bs;

    for (int i = lt; i < 512; i += 128) sh_h2[bs*512 + i] = hn[b*512 + i];
    __syncthreads();

    float a = 0.f;
    #pragma unroll 8
    for (int k = 0; k < 512; k++)
        a += g_WpT[k*128 + lt] * sh_h2[bs*512 + k];
    float y = a + ((lt < 123) ? bfc[lt] : 0.f);
    sh_y[bs*128 + lt] = y;
    __syncthreads();

    if (lt < 32) {                           // pi softmax stats over y[3..23)
        float v = (lt >= 3 && lt < 23) ? sh_y[bs*128 + lt] : -1e30f;
        float m = v;
        #pragma unroll
        for (int o = 16; o; o >>= 1) m = fmaxf(m, __shfl_xor_sync(0xffffffffu, m, o));
        float e = (lt >= 3 && lt < 23) ? expf(v - m) : 0.f;
        float s = e;
        #pragma unroll
        for (int o = 16; o; o >>= 1) s += __shfl_xor_sync(0xffffffffu, s, o);
        if (lt == 0) { sh_mx[bs] = m; sh_inv[bs] = 1.f / s; }
    }
    __syncthreads();

    if (lt < 123) {
        int row = b*257 + t;
        if (lt < 3)        out[6*OFF + row*3 + lt] = y;                           // pen logits
        else if (lt < 23)  out[          row*20 + (lt-3)]   = expf(y - sh_mx[bs]) * sh_inv[bs];
        else if (lt < 43)  out[1*OFF +  row*20 + (lt-23)]  = y;                   // mu1
        else if (lt < 63)  out[2*OFF +  row*20 + (lt-43)]  = y;                   // mu2
        else if (lt < 83)  out[3*OFF +  row*20 + (lt-63)]  = expf(y);             // s1
        else if (lt < 103) out[4*OFF +  row*20 + (lt-83)]  = expf(y);             // s2
        else               out[5*OFF +  row*20 + (lt-103)] = tanhf(y);            // corr
    }
}

// ---------------- launcher ----------------
extern "C" void kernel_launch(void* const* d_in, const int* in_sizes, int n_in,
                              void* d_out, int out_size)
{
    const float* backbone = (const float*)d_in[0];
    const float* z        = (const float*)d_in[1];
    const float* sketch   = (const float*)d_in[2];
    const float* Whc      = (const float*)d_in[3];
    const float* bhc      = (const float*)d_in[4];
    const float* Wch      = (const float*)d_in[5];
    const float* bch      = (const float*)d_in[6];
    const float* Kconv    = (const float*)d_in[7];
    const float* bconvf   = (const float*)d_in[8];
    const float* Watt     = (const float*)d_in[9];
    const float* batt     = (const float*)d_in[10];
    const float* Wih      = (const float*)d_in[11];
    const float* Whh      = (const float*)d_in[12];
    const float* bih      = (const float*)d_in[13];
    const float* bhh      = (const float*)d_in[14];
    const float* Wp       = (const float*)d_in[15];
    const float* bfc      = (const float*)d_in[16];
    float* out = (float*)d_out;
    (void)in_sizes; (void)n_in; (void)out_size;

    pack_kernel<<<32768, 256>>>(Wih, Whh, Wch, Wp, Kconv, backbone, bih, bhh);
    init_hc_kernel<<<64, 256>>>(z, Whc, bhc);
    conv_kernel<<<dim3(256, 4), 256>>>(backbone, bconvf);
    gem0_kernel<<<128, 256>>>(bch);

    for (int t = 0; t < TT; t++) {
        attn_kernel<<<256, 256>>>(Watt, batt, t);
        gates_kernel<<<dim3(4, 32), 256>>>(sketch, t);
        head_gem_kernel<<<256, 256>>>(bfc, out, bch, t);
    }
}

// round 14
// speedup vs baseline: 1.0036x; 1.0036x over previous
#include <cuda_runtime.h>
#include <math.h>

#define BATCH 256
#define TT    257
#define HID   512
#define EMB   256
#define CF    512
#define HW    64
#define NMIX  20
#define KP    1040            // gates K padded: 512(att)+5(pt)+512(h)=1029 -> 1040
#define OUTROWS (BATCH*TT)    // 65792
#define OFF   (OUTROWS*NMIX)  // 1315840

// ---------------- device scratch (no allocs allowed) ----------------
__device__ float g_WgT [KP*2048];      // gates weights, K-major  (8.5 MB)
__device__ float g_WkT [4608*256];     // conv weights, K-major   (4.7 MB)
__device__ float g_WchT[512*256];      // W_conv_h transposed (K-major)
__device__ float g_orgT[BATCH*HW*CF];  // backbone transposed to [b][hw][c] (33.5 MB)
__device__ float g_xem [BATCH*HW*EMB]; // conv output [b][hw][e]  (16.8 MB)
__device__ float g_gem [BATCH*EMB];    // per-step g_em
__device__ float g_hbuf[2][BATCH*HID];
__device__ float g_c   [BATCH*HID];
__device__ float g_att [BATCH*CF];

__device__ __forceinline__ float sigm(float x) { return 1.f / (1.f + expf(-x)); }
__device__ __forceinline__ float ftanh(float x) {
    float y; asm("tanh.approx.f32 %0, %1;" : "=f"(y) : "f"(x)); return y;
}

// ---------------- one-time pack / transpose ----------------
__global__ void pack_kernel(const float* __restrict__ Wih, const float* __restrict__ Whh,
                            const float* __restrict__ Wch, const float* __restrict__ Kc,
                            const float* __restrict__ bb)
{
    int i = blockIdx.x * 256 + threadIdx.x;
    if (i < KP*2048) {                       // WgT[k][j]
        int k = i / 2048, j = i - k*2048;
        float v = 0.f;
        if (k < 517)       v = Wih[j*517 + k];
        else if (k < 1029) v = Whh[j*512 + (k-517)];
        g_WgT[i] = v;
    }
    if (i < 4608*256) {                      // WkT[c*9+tap][e]
        int k = i >> 8, e = i & 255;
        int c = k / 9, tap = k - c*9;
        g_WkT[i] = Kc[(e*512 + c)*9 + tap];
    }
    if (i < 512*256) {                       // WchT[k][e]
        int k = i >> 8, e = i & 255;
        g_WchT[i] = Wch[e*512 + k];
    }
    if (i < BATCH*HW*CF) {                   // orgT[b][hw][c]
        int c = i & 511; int hw = (i >> 9) & 63; int b = i >> 15;
        g_orgT[i] = bb[(b*CF + c)*HW + hw];
    }
}

// ---------------- h0/c0 = tanh(z @ W_fc_hc^T + b) ----------------
__global__ void init_hc_kernel(const float* __restrict__ z, const float* __restrict__ Whc,
                               const float* __restrict__ bhc)
{
    __shared__ float sh_z[4*128];
    int tid = threadIdx.x;                   // 256
    int b0 = blockIdx.x * 4;
    for (int i = tid; i < 512; i += 256) sh_z[i] = z[b0*128 + i];
    __syncthreads();
    for (int jj = tid; jj < 1024; jj += 256) {
        float a0 = 0.f, a1 = 0.f, a2 = 0.f, a3 = 0.f;
        for (int k = 0; k < 128; k++) {
            float w = Whc[jj*128 + k];
            a0 += w * sh_z[k];       a1 += w * sh_z[128 + k];
            a2 += w * sh_z[256 + k]; a3 += w * sh_z[384 + k];
        }
        float bv = bhc[jj];
        float v[4] = { tanhf(a0+bv), tanhf(a1+bv), tanhf(a2+bv), tanhf(a3+bv) };
        #pragma unroll
        for (int b = 0; b < 4; b++) {
            if (jj < 512) g_hbuf[0][(b0+b)*512 + jj]      = v[b];
            else          g_c     [(b0+b)*512 + (jj-512)] = v[b];
        }
    }
}

// ---------------- conv3x3 SAME as implicit GEMM: xem[m][e], M=B*HW, K=4608 ----------------
__global__ void conv_kernel(const float* __restrict__ bb, const float* __restrict__ bconv)
{
    __shared__ float As[16*68];
    __shared__ float Bs[16*64];
    int tid = threadIdx.x;
    int m0 = blockIdx.x * 64;
    int n0 = blockIdx.y * 64;
    int tx = tid & 15, ty = tid >> 4;
    float acc[4][4] = {};

    int lmm = tid & 63, lkb = tid >> 6;      // loader roles
    int m = m0 + lmm;
    int bidx = m >> 6, pix = m & 63, py = pix >> 3, px = pix & 7;

    for (int kt = 0; kt < 4608; kt += 16) {
        #pragma unroll
        for (int i = 0; i < 4; i++) {        // A tile (patches)
            int kk = lkb*4 + i; int k = kt + kk;
            int c = k / 9, tap = k - c*9;
            int dy = tap / 3, dx = tap - dy*3;
            int yy = py + dy - 1, xx = px + dx - 1;
            float v = 0.f;
            if (yy >= 0 && yy < 8 && xx >= 0 && xx < 8)
                v = bb[((bidx*CF + c) << 6) + yy*8 + xx];
            As[kk*68 + lmm] = v;
        }
        #pragma unroll
        for (int i = 0; i < 4; i++) {        // B tile (weights, coalesced)
            int kk = lkb*4 + i;
            Bs[kk*64 + lmm] = g_WkT[(kt+kk)*256 + n0 + lmm];
        }
        __syncthreads();
        #pragma unroll
        for (int kk = 0; kk < 16; kk++) {
            float4 a  = *(const float4*)&As[kk*68 + ty*4];
            float4 bv = *(const float4*)&Bs[kk*64 + tx*4];
            acc[0][0] += a.x*bv.x; acc[0][1] += a.x*bv.y; acc[0][2] += a.x*bv.z; acc[0][3] += a.x*bv.w;
            acc[1][0] += a.y*bv.x; acc[1][1] += a.y*bv.y; acc[1][2] += a.y*bv.z; acc[1][3] += a.y*bv.w;
            acc[2][0] += a.z*bv.x; acc[2][1] += a.z*bv.y; acc[2][2] += a.z*bv.z; acc[2][3] += a.z*bv.w;
            acc[3][0] += a.w*bv.x; acc[3][1] += a.w*bv.y; acc[3][2] += a.w*bv.z; acc[3][3] += a.w*bv.w;
        }
        __syncthreads();
    }
    int e0 = n0 + tx*4;
    float b0v = bconv[e0], b1v = bconv[e0+1], b2v = bconv[e0+2], b3v = bconv[e0+3];
    #pragma unroll
    for (int r = 0; r < 4; r++) {
        int mm = m0 + ty*4 + r;
        float4 o;
        o.x = acc[r][0] + b0v; o.y = acc[r][1] + b1v;
        o.z = acc[r][2] + b2v; o.w = acc[r][3] + b3v;
        *(float4*)&g_xem[mm*256 + e0] = o;
    }
}

// ---------------- gem helper: g_em = h @ WchT + b, smem-staged weights ----------------
// Block: 16 batches x 32 cols. sbuf: [0,8192) = h tile, [8192,12288) = weight chunk.
__device__ __forceinline__ void gem_block(const float* __restrict__ hsrc,
                                          const float* __restrict__ bconvh,
                                          float* sbuf, int bid, int tid)
{
    float* sh_h = sbuf;
    float* sh_w = sbuf + 8192;
    int bg = (bid >> 3) * 16;
    int cg = (bid & 7) * 32;

    for (int i = tid; i < 8192; i += 256) sh_h[i] = hsrc[bg*512 + i];

    int wid = tid >> 5, lane = tid & 31;
    const float* h0 = &sh_h[(wid*2)*512];
    const float* h1 = &sh_h[(wid*2+1)*512];
    float a0 = 0.f, a1 = 0.f;

    for (int kc = 0; kc < 512; kc += 128) {
        __syncthreads();
        for (int i = tid; i < 128*32; i += 256)      // coalesced: 32-float rows
            sh_w[i] = g_WchT[(kc + (i >> 5))*256 + cg + (i & 31)];
        __syncthreads();
        #pragma unroll 8
        for (int k2 = 0; k2 < 128; k2++) {
            float w = sh_w[k2*32 + lane];            // conflict-free
            a0 += w * h0[kc + k2];
            a1 += w * h1[kc + k2];
        }
    }
    float bv = bconvh[cg + lane];
    g_gem[(bg + wid*2    )*256 + cg + lane] = a0 + bv;
    g_gem[(bg + wid*2 + 1)*256 + cg + lane] = a1 + bv;
}

// ---------------- pre-loop gem for t=0 ----------------
__global__ void gem0_kernel(const float* __restrict__ bconvh)
{
    __shared__ float sbuf[12288];
    gem_block(g_hbuf[0], bconvh, sbuf, blockIdx.x, threadIdx.x);
}

// ---------------- per-step: tanh attention + softmax + att reduce (1 batch / block) -------
__global__ void attn_kernel(const float* __restrict__ watt, const float* __restrict__ batt,
                            int t)
{
    __shared__ float sh_gem[256];
    __shared__ float sh_w[256];
    __shared__ float sh_sc[64];
    int tid = threadIdx.x;                   // 256
    int b = blockIdx.x;

    sh_gem[tid] = g_gem[b*256 + tid];
    sh_w[tid]   = watt[tid];
    __syncthreads();

    int wid = tid >> 5, lane = tid & 31;
    float bav = batt[0];
    const float4* gem4 = (const float4*)sh_gem;
    const float4* w4   = (const float4*)sh_w;
    float4 gA = gem4[2*lane], gB = gem4[2*lane+1];
    float4 wA = w4[2*lane],   wB = w4[2*lane+1];

    #pragma unroll
    for (int hw = wid; hw < 64; hw += 8) {   // scores
        const float4* xr = (const float4*)&g_xem[(b*64 + hw)*256];
        float4 x0 = xr[2*lane], x1 = xr[2*lane+1];
        float s;
        s  = wA.x * ftanh(x0.x + gA.x);
        s += wA.y * ftanh(x0.y + gA.y);
        s += wA.z * ftanh(x0.z + gA.z);
        s += wA.w * ftanh(x0.w + gA.w);
        s += wB.x * ftanh(x1.x + gB.x);
        s += wB.y * ftanh(x1.y + gB.y);
        s += wB.z * ftanh(x1.z + gB.z);
        s += wB.w * ftanh(x1.w + gB.w);
        #pragma unroll
        for (int o = 16; o; o >>= 1) s += __shfl_xor_sync(0xffffffffu, s, o);
        if (lane == 0) sh_sc[hw] = s + bav;
    }
    __syncthreads();

    if (wid == 0) {                          // softmax over 64
        float v0 = sh_sc[lane], v1 = sh_sc[32 + lane];
        float m = fmaxf(v0, v1);
        #pragma unroll
        for (int o = 16; o; o >>= 1) m = fmaxf(m, __shfl_xor_sync(0xffffffffu, m, o));
        float e0 = expf(v0 - m), e1 = expf(v1 - m);
        float s = e0 + e1;
        #pragma unroll
        for (int o = 16; o; o >>= 1) s += __shfl_xor_sync(0xffffffffu, s, o);
        float inv = 1.f / s;
        sh_sc[lane] = e0*inv; sh_sc[32 + lane] = e1*inv;
    }
    __syncthreads();

    {                                        // att = alpha @ orgfeat  (2 cols / thread)
        const float* org = &g_orgT[b*64*512];
        float a0 = 0.f, a1 = 0.f;
        #pragma unroll 8
        for (int hw = 0; hw < 64; hw++) {
            float al = sh_sc[hw];
            a0 += al * org[hw*512 + tid];
            a1 += al * org[hw*512 + 256 + tid];
        }
        g_att[b*512 + tid]       = a0;
        g_att[b*512 + 256 + tid] = a1;
    }
}

// ---------------- per-step: gates GEMM (M=256,N=2048,K=1029pad) + LSTM cell ----------------
__global__ void gates_kernel(const float* __restrict__ bih, const float* __restrict__ bhh,
                             const float* __restrict__ sketch, int t)
{
    __shared__ float As[16*34];              // [kk][mm], padded
    __shared__ float Bs[16*16*4];            // [kk][unit][gate]
    int tid = threadIdx.x;                   // 256
    int m0 = blockIdx.x * 32;
    int u0 = blockIdx.y * 16;
    int tx = tid & 15, ty = tid >> 4;
    const float* hcur  = g_hbuf[t & 1];
    float*       hnext = g_hbuf[(t + 1) & 1];
    float acc[2][4] = {};

    int lmm = tid >> 3;                      // 0..31
    int lkq = (tid & 7) * 2;                 // 0,2,..,14
    int lrow = m0 + lmm;

    for (int kt = 0; kt < KP; kt += 16) {
        #pragma unroll
        for (int i = 0; i < 2; i++) {        // A = concat(att, pt, h) built on the fly
            int kk = lkq + i; int k = kt + kk;
            float v;
            if (k < 512)       v = g_att[lrow*512 + k];
            else if (k < 517)  { int kp = k - 512;
                                 v = (t == 0) ? (kp == 2 ? 1.f : 0.f)
                                              : sketch[((t-1)*BATCH + lrow)*5 + kp]; }
            else if (k < 1029) v = hcur[lrow*512 + (k - 517)];
            else               v = 0.f;
            As[kk*34 + lmm] = v;
        }
        #pragma unroll
        for (int r = 0; r < 4; r++) {        // B tile from packed WgT
            int idx = tid + r*256;
            int kk = idx >> 6; int rem = idx & 63; int gg = rem >> 4; int ul = rem & 15;
            Bs[(kk*16 + ul)*4 + gg] = g_WgT[(kt+kk)*2048 + gg*512 + u0 + ul];
        }
        __syncthreads();
        #pragma unroll
        for (int kk = 0; kk < 16; kk++) {
            float2 a  = *(const float2*)&As[kk*34 + ty*2];
            float4 bv = *(const float4*)&Bs[(kk*16 + tx)*4];
            acc[0][0] += a.x*bv.x; acc[0][1] += a.x*bv.y; acc[0][2] += a.x*bv.z; acc[0][3] += a.x*bv.w;
            acc[1][0] += a.y*bv.x; acc[1][1] += a.y*bv.y; acc[1][2] += a.y*bv.z; acc[1][3] += a.y*bv.w;
        }
        __syncthreads();
    }

    int u = u0 + tx;
    float bs0 = bih[u]        + bhh[u];
    float bs1 = bih[512 + u]  + bhh[512 + u];
    float bs2 = bih[1024 + u] + bhh[1024 + u];
    float bs3 = bih[1536 + u] + bhh[1536 + u];
    #pragma unroll
    for (int r = 0; r < 2; r++) {
        int row = m0 + ty*2 + r;
        float iv = acc[r][0] + bs0;
        float fv = acc[r][1] + bs1;
        float gv = acc[r][2] + bs2;
        float ov = acc[r][3] + bs3;
        float co = g_c[row*512 + u];
        float cn = sigm(fv)*co + sigm(iv)*tanhf(gv);
        float hn = sigm(ov)*tanhf(cn);
        g_c[row*512 + u] = cn;
        hnext[row*512 + u] = hn;
    }
}

// ---------------- per-step fused: head(t) [blocks 128..255] + gem(t+1) [blocks 0..127] ----
// Both read hbuf[(t+1)&1], written by gates(t). Independent outputs.
__global__ void head_gem_kernel(const float* __restrict__ bfc, float* __restrict__ out,
                                const float* __restrict__ bconvh,
                                const float* __restrict__ Wp, int t)
{
    __shared__ float sbuf[12288];            // gem: h(8192)+w(4096); head: aliased below
    int tid = threadIdx.x;                   // 256
    const float* hn = g_hbuf[(t + 1) & 1];

    if (blockIdx.x < 128) {                  // ---- gem for step t+1 ----
        gem_block(hn, bconvh, sbuf, blockIdx.x, tid);
        return;
    }

    // ---- head for 2 batches ----
    float* sh_h2  = sbuf;                    // 2*512
    float* sh_y   = sbuf + 1024;             // 2*128
    float* sh_mx  = sbuf + 1280;             // 2
    float* sh_inv = sbuf + 1282;             // 2
    int bs = tid >> 7;                       // batch slot 0/1
    int lt = tid & 127;
    int b = (blockIdx.x - 128)*2 + bs;

    for (int i = lt; i < 512; i += 128) sh_h2[bs*512 + i] = hn[b*512 + i];
    __syncthreads();

    float a = 0.f;
    if (lt < 123) {                          // row-contiguous Wp stream, MLP-rich
        const float4* wr = (const float4*)&Wp[lt*512];
        const float4* hv = (const float4*)&sh_h2[bs*512];
        #pragma unroll 8
        for (int i = 0; i < 128; i++) {
            float4 w = wr[i], h = hv[i];
            a += w.x*h.x + w.y*h.y + w.z*h.z + w.w*h.w;
        }
    }
    float y = a + ((lt < 123) ? bfc[lt] : 0.f);
    sh_y[bs*128 + lt] = y;
    __syncthreads();

    if (lt < 32) {                           // pi softmax stats over y[3..23)
        float v = (lt >= 3 && lt < 23) ? sh_y[bs*128 + lt] : -1e30f;
        float m = v;
        #pragma unroll
        for (int o = 16; o; o >>= 1) m = fmaxf(m, __shfl_xor_sync(0xffffffffu, m, o));
        float e = (lt >= 3 && lt < 23) ? expf(v - m) : 0.f;
        float s = e;
        #pragma unroll
        for (int o = 16; o; o >>= 1) s += __shfl_xor_sync(0xffffffffu, s, o);
        if (lt == 0) { sh_mx[bs] = m; sh_inv[bs] = 1.f / s; }
    }
    __syncthreads();

    if (lt < 123) {
        int row = b*257 + t;
        if (lt < 3)        out[6*OFF + row*3 + lt] = y;                           // pen logits
        else if (lt < 23)  out[          row*20 + (lt-3)]   = expf(y - sh_mx[bs]) * sh_inv[bs];
        else if (lt < 43)  out[1*OFF +  row*20 + (lt-23)]  = y;                   // mu1
        else if (lt < 63)  out[2*OFF +  row*20 + (lt-43)]  = y;                   // mu2
        else if (lt < 83)  out[3*OFF +  row*20 + (lt-63)]  = expf(y);             // s1
        else if (lt < 103) out[4*OFF +  row*20 + (lt-83)]  = expf(y);             // s2
        else               out[5*OFF +  row*20 + (lt-103)] = tanhf(y);            // corr
    }
}

// ---------------- launcher ----------------
extern "C" void kernel_launch(void* const* d_in, const int* in_sizes, int n_in,
                              void* d_out, int out_size)
{
    const float* backbone = (const float*)d_in[0];
    const float* z        = (const float*)d_in[1];
    const float* sketch   = (const float*)d_in[2];
    const float* Whc      = (const float*)d_in[3];
    const float* bhc      = (const float*)d_in[4];
    const float* Wch      = (const float*)d_in[5];
    const float* bch      = (const float*)d_in[6];
    const float* Kconv    = (const float*)d_in[7];
    const float* bconvf   = (const float*)d_in[8];
    const float* Watt     = (const float*)d_in[9];
    const float* batt     = (const float*)d_in[10];
    const float* Wih      = (const float*)d_in[11];
    const float* Whh      = (const float*)d_in[12];
    const float* bih      = (const float*)d_in[13];
    const float* bhh      = (const float*)d_in[14];
    const float* Wp       = (const float*)d_in[15];
    const float* bfc      = (const float*)d_in[16];
    float* out = (float*)d_out;
    (void)in_sizes; (void)n_in; (void)out_size;

    pack_kernel<<<32768, 256>>>(Wih, Whh, Wch, Kconv, backbone);
    init_hc_kernel<<<64, 256>>>(z, Whc, bhc);
    conv_kernel<<<dim3(256, 4), 256>>>(backbone, bconvf);
    gem0_kernel<<<128, 256>>>(bch);

    for (int t = 0; t < TT; t++) {
        attn_kernel<<<256, 256>>>(Watt, batt, t);
        gates_kernel<<<dim3(8, 32), 256>>>(bih, bhh, sketch, t);
        head_gem_kernel<<<256, 256>>>(bfc, out, bch, Wp, t);
    }
}

// round 15
// speedup vs baseline: 1.6924x; 1.6863x over previous
#include <cuda_runtime.h>
#include <math.h>

#define BATCH 256
#define TT    257
#define HID   512
#define EMB   256
#define CF    512
#define HW    64
#define NMIX  20
#define KPM   1056            // gates K padded: 512(att)+5(pt)+512(h)=1029 -> 33 tiles of 32
#define NT    33              // K tiles
#define OUTROWS (BATCH*TT)    // 65792
#define OFF   (OUTROWS*NMIX)  // 1315840

// ---------------- device scratch (no allocs allowed) ----------------
__device__ float g_WgT [KPM*2048];     // gates weights, K-major, tf32-rna, cols j'=unit*4+gate
__device__ float g_bias2[2048];        // bih+bhh in j' order
__device__ float g_WkT [4608*256];     // conv weights, K-major
__device__ float g_WchT[512*256];      // W_conv_h transposed (K-major)
__device__ float g_orgT[BATCH*HW*CF];  // backbone transposed to [b][hw][c]
__device__ float g_xem [BATCH*HW*EMB]; // conv output [b][hw][e]
__device__ float g_gem [BATCH*EMB];    // per-step g_em
__device__ float g_act [2][BATCH*KPM]; // MMA A operand: [att|pt|h|0], tf32-rounded, per parity
__device__ float g_hbuf[2][BATCH*HID]; // full-precision h
__device__ float g_c   [BATCH*HID];

__device__ __forceinline__ float sigm(float x) { return 1.f / (1.f + expf(-x)); }
__device__ __forceinline__ float ftanh(float x) {
    float y; asm("tanh.approx.f32 %0, %1;" : "=f"(y) : "f"(x)); return y;
}
__device__ __forceinline__ float to_tf32(float v) {
    unsigned u; asm("cvt.rna.tf32.f32 %0, %1;" : "=r"(u) : "f"(v));
    return __uint_as_float(u);
}
__device__ __forceinline__ unsigned smaddr(const void* p) {
    return (unsigned)__cvta_generic_to_shared(p);
}

// ---------------- one-time pack / transpose ----------------
__global__ void pack_kernel(const float* __restrict__ Wih, const float* __restrict__ Whh,
                            const float* __restrict__ Wch, const float* __restrict__ Kc,
                            const float* __restrict__ bb,
                            const float* __restrict__ bih, const float* __restrict__ bhh)
{
    int i = blockIdx.x * 256 + threadIdx.x;
    if (i < KPM*2048) {                      // WgT[k][j'], j' = unit*4+gate, tf32-rna
        int k = i / 2048, jp = i - k*2048;
        int u = jp >> 2, g = jp & 3;
        int j = g*512 + u;
        float v = 0.f;
        if (k < 517)       v = Wih[j*517 + k];
        else if (k < 1029) v = Whh[j*512 + (k-517)];
        g_WgT[i] = to_tf32(v);
    }
    if (i < 2048) {                          // combined bias in j' order
        int u = i >> 2, g = i & 3;
        int j = g*512 + u;
        g_bias2[i] = bih[j] + bhh[j];
    }
    if (i < 2*BATCH*KPM)                     // zero activation pad regions
        ((float*)g_act)[i] = 0.f;
    if (i < 4608*256) {                      // WkT[c*9+tap][e]
        int k = i >> 8, e = i & 255;
        int c = k / 9, tap = k - c*9;
        g_WkT[i] = Kc[(e*512 + c)*9 + tap];
    }
    if (i < 512*256) {                       // WchT[k][e]
        int k = i >> 8, e = i & 255;
        g_WchT[i] = Wch[e*512 + k];
    }
    if (i < BATCH*HW*CF) {                   // orgT[b][hw][c]
        int c = i & 511; int hw = (i >> 9) & 63; int b = i >> 15;
        g_orgT[i] = bb[(b*CF + c)*HW + hw];
    }
}

// ---------------- h0/c0 = tanh(z @ W_fc_hc^T + b) ----------------
__global__ void init_hc_kernel(const float* __restrict__ z, const float* __restrict__ Whc,
                               const float* __restrict__ bhc)
{
    __shared__ float sh_z[4*128];
    int tid = threadIdx.x;                   // 256
    int b0 = blockIdx.x * 4;
    for (int i = tid; i < 512; i += 256) sh_z[i] = z[b0*128 + i];
    __syncthreads();
    for (int jj = tid; jj < 1024; jj += 256) {
        float a0 = 0.f, a1 = 0.f, a2 = 0.f, a3 = 0.f;
        for (int k = 0; k < 128; k++) {
            float w = Whc[jj*128 + k];
            a0 += w * sh_z[k];       a1 += w * sh_z[128 + k];
            a2 += w * sh_z[256 + k]; a3 += w * sh_z[384 + k];
        }
        float bv = bhc[jj];
        float v[4] = { tanhf(a0+bv), tanhf(a1+bv), tanhf(a2+bv), tanhf(a3+bv) };
        #pragma unroll
        for (int b = 0; b < 4; b++) {
            if (jj < 512) {
                g_hbuf[0][(b0+b)*512 + jj] = v[b];
                g_act[0][(b0+b)*KPM + 517 + jj] = to_tf32(v[b]);
            } else {
                g_c[(b0+b)*512 + (jj-512)] = v[b];
            }
        }
    }
}

// ---------------- conv3x3 SAME as implicit GEMM: xem[m][e], M=B*HW, K=4608 ----------------
__global__ void conv_kernel(const float* __restrict__ bb, const float* __restrict__ bconv)
{
    __shared__ float As[16*68];
    __shared__ float Bs[16*64];
    int tid = threadIdx.x;
    int m0 = blockIdx.x * 64;
    int n0 = blockIdx.y * 64;
    int tx = tid & 15, ty = tid >> 4;
    float acc[4][4] = {};

    int lmm = tid & 63, lkb = tid >> 6;      // loader roles
    int m = m0 + lmm;
    int bidx = m >> 6, pix = m & 63, py = pix >> 3, px = pix & 7;

    for (int kt = 0; kt < 4608; kt += 16) {
        #pragma unroll
        for (int i = 0; i < 4; i++) {        // A tile (patches)
            int kk = lkb*4 + i; int k = kt + kk;
            int c = k / 9, tap = k - c*9;
            int dy = tap / 3, dx = tap - dy*3;
            int yy = py + dy - 1, xx = px + dx - 1;
            float v = 0.f;
            if (yy >= 0 && yy < 8 && xx >= 0 && xx < 8)
                v = bb[((bidx*CF + c) << 6) + yy*8 + xx];
            As[kk*68 + lmm] = v;
        }
        #pragma unroll
        for (int i = 0; i < 4; i++) {        // B tile (weights, coalesced)
            int kk = lkb*4 + i;
            Bs[kk*64 + lmm] = g_WkT[(kt+kk)*256 + n0 + lmm];
        }
        __syncthreads();
        #pragma unroll
        for (int kk = 0; kk < 16; kk++) {
            float4 a  = *(const float4*)&As[kk*68 + ty*4];
            float4 bv = *(const float4*)&Bs[kk*64 + tx*4];
            acc[0][0] += a.x*bv.x; acc[0][1] += a.x*bv.y; acc[0][2] += a.x*bv.z; acc[0][3] += a.x*bv.w;
            acc[1][0] += a.y*bv.x; acc[1][1] += a.y*bv.y; acc[1][2] += a.y*bv.z; acc[1][3] += a.y*bv.w;
            acc[2][0] += a.z*bv.x; acc[2][1] += a.z*bv.y; acc[2][2] += a.z*bv.z; acc[2][3] += a.z*bv.w;
            acc[3][0] += a.w*bv.x; acc[3][1] += a.w*bv.y; acc[3][2] += a.w*bv.z; acc[3][3] += a.w*bv.w;
        }
        __syncthreads();
    }
    int e0 = n0 + tx*4;
    float b0v = bconv[e0], b1v = bconv[e0+1], b2v = bconv[e0+2], b3v = bconv[e0+3];
    #pragma unroll
    for (int r = 0; r < 4; r++) {
        int mm = m0 + ty*4 + r;
        float4 o;
        o.x = acc[r][0] + b0v; o.y = acc[r][1] + b1v;
        o.z = acc[r][2] + b2v; o.w = acc[r][3] + b3v;
        *(float4*)&g_xem[mm*256 + e0] = o;
    }
}

// ---------------- gem helper: g_em = h @ WchT + b (8 batches x 32 cols / block) ----------
__device__ __forceinline__ void gem_block(const float* __restrict__ hsrc,
                                          const float* __restrict__ bconvh,
                                          float* sbuf, int bid, int tid)
{
    float* sh_h = sbuf;                      // 8*512
    float* sh_w = sbuf + 4096;               // 128*32
    int bg = (bid >> 3) * 8;
    int cg = (bid & 7) * 32;

    for (int i = tid; i < 4096; i += 256) sh_h[i] = hsrc[bg*512 + i];

    int wid = tid >> 5, lane = tid & 31;
    const float* hrow = &sh_h[wid*512];
    float a = 0.f;

    for (int kc = 0; kc < 512; kc += 128) {
        __syncthreads();
        for (int i = tid; i < 4096; i += 256)    // coalesced 32-float rows
            sh_w[i] = g_WchT[(kc + (i >> 5))*256 + cg + (i & 31)];
        __syncthreads();
        #pragma unroll 8
        for (int k2 = 0; k2 < 128; k2++)
            a += sh_w[k2*32 + lane] * hrow[kc + k2];
    }
    g_gem[(bg + wid)*256 + cg + lane] = a + bconvh[cg + lane];
}

// ---------------- pre-loop gem for t=0 ----------------
__global__ void gem0_kernel(const float* __restrict__ bconvh)
{
    __shared__ float sbuf[8192];
    gem_block(g_hbuf[0], bconvh, sbuf, blockIdx.x, threadIdx.x);
}

// ---------------- per-step: attention; writes att+pt (tf32) into g_act[t&1] --------------
__global__ void attn_kernel(const float* __restrict__ watt, const float* __restrict__ batt,
                            const float* __restrict__ sketch, int t)
{
    __shared__ float sh_gem[256];
    __shared__ float sh_w[256];
    __shared__ float sh_sc[64];
    int tid = threadIdx.x;                   // 256
    int b = blockIdx.x;
    float* act = g_act[t & 1] + b*KPM;

    sh_gem[tid] = g_gem[b*256 + tid];
    sh_w[tid]   = watt[tid];
    __syncthreads();

    int wid = tid >> 5, lane = tid & 31;
    float bav = batt[0];
    const float4* gem4 = (const float4*)sh_gem;
    const float4* w4   = (const float4*)sh_w;
    float4 gA = gem4[2*lane], gB = gem4[2*lane+1];
    float4 wA = w4[2*lane],   wB = w4[2*lane+1];

    #pragma unroll
    for (int hw = wid; hw < 64; hw += 8) {   // scores
        const float4* xr = (const float4*)&g_xem[(b*64 + hw)*256];
        float4 x0 = xr[2*lane], x1 = xr[2*lane+1];
        float s;
        s  = wA.x * ftanh(x0.x + gA.x);
        s += wA.y * ftanh(x0.y + gA.y);
        s += wA.z * ftanh(x0.z + gA.z);
        s += wA.w * ftanh(x0.w + gA.w);
        s += wB.x * ftanh(x1.x + gB.x);
        s += wB.y * ftanh(x1.y + gB.y);
        s += wB.z * ftanh(x1.z + gB.z);
        s += wB.w * ftanh(x1.w + gB.w);
        #pragma unroll
        for (int o = 16; o; o >>= 1) s += __shfl_xor_sync(0xffffffffu, s, o);
        if (lane == 0) sh_sc[hw] = s + bav;
    }
    __syncthreads();

    if (wid == 0) {                          // softmax over 64
        float v0 = sh_sc[lane], v1 = sh_sc[32 + lane];
        float m = fmaxf(v0, v1);
        #pragma unroll
        for (int o = 16; o; o >>= 1) m = fmaxf(m, __shfl_xor_sync(0xffffffffu, m, o));
        float e0 = expf(v0 - m), e1 = expf(v1 - m);
        float s = e0 + e1;
        #pragma unroll
        for (int o = 16; o; o >>= 1) s += __shfl_xor_sync(0xffffffffu, s, o);
        float inv = 1.f / s;
        sh_sc[lane] = e0*inv; sh_sc[32 + lane] = e1*inv;
    }
    __syncthreads();

    {                                        // att = alpha @ orgfeat  (2 cols / thread)
        const float* org = &g_orgT[b*64*512];
        float a0 = 0.f, a1 = 0.f;
        #pragma unroll 8
        for (int hw = 0; hw < 64; hw++) {
            float al = sh_sc[hw];
            a0 += al * org[hw*512 + tid];
            a1 += al * org[hw*512 + 256 + tid];
        }
        act[tid]       = to_tf32(a0);
        act[256 + tid] = to_tf32(a1);
    }
    if (tid < 5) {                           // pt for this step
        float v = (t == 0) ? (tid == 2 ? 1.f : 0.f)
                           : sketch[((t-1)*BATCH + b)*5 + tid];
        act[512 + tid] = to_tf32(v);
    }
}

// ---------------- per-step: gates GEMM (tf32 mma, cp.async double-buffered) + LSTM -------
// Block 64(M) x 64(N), K-tile 32. 8 warps = 4M x 2N; warp m16 x n32.
// Columns j' = unit*4+gate; lane pairs own the 4 gates of one unit.
__global__ void gates_kernel(int t)
{
    __shared__ float As[2][64*36];           // [m][k], stride 36 (144B rows, 16B aligned)
    __shared__ float Bs[2][32*72];           // [k][n], stride 72 (288B rows, 16B aligned)
    int tid = threadIdx.x;                   // 256
    int m0 = blockIdx.x * 64;
    int n0 = blockIdx.y * 64;
    const float* act  = g_act[t & 1];
    float*       hnext = g_hbuf[(t + 1) & 1];
    float*       actn  = g_act[(t + 1) & 1];
    int wid = tid >> 5, lane = tid & 31;
    int wm = (wid & 3) * 16, wn = (wid >> 2) * 32;
    int lq = lane >> 2, lr = lane & 3;
    float acc[4][4] = {};

    auto issue = [&](int kt, int buf) {
        #pragma unroll
        for (int h = 0; h < 2; h++) {        // A: 512 x 16B chunks
            int c = tid + h*256;
            int r = c >> 3, o = (c & 7) * 4;
            asm volatile("cp.async.ca.shared.global [%0], [%1], 16;" ::
                "r"(smaddr(&As[buf][r*36 + o])), "l"(&act[(m0 + r)*KPM + kt + o]));
        }
        #pragma unroll
        for (int h = 0; h < 2; h++) {        // B: 512 x 16B chunks
            int c = tid + h*256;
            int r = c >> 4, o = (c & 15) * 4;
            asm volatile("cp.async.ca.shared.global [%0], [%1], 16;" ::
                "r"(smaddr(&Bs[buf][r*72 + o])), "l"(&g_WgT[(kt + r)*2048 + n0 + o]));
        }
        asm volatile("cp.async.commit_group;");
    };

    issue(0, 0);
    for (int it = 0; it < NT; it++) {
        int buf = it & 1;
        if (it + 1 < NT) {
            issue((it + 1)*32, buf ^ 1);
            asm volatile("cp.async.wait_group 1;");
        } else {
            asm volatile("cp.async.wait_group 0;");
        }
        __syncthreads();
        #pragma unroll
        for (int kf = 0; kf < 4; kf++) {
            int kb = kf*8;
            unsigned a0 = __float_as_uint(As[buf][(wm + lq    )*36 + kb + lr    ]);
            unsigned a1 = __float_as_uint(As[buf][(wm + lq + 8)*36 + kb + lr    ]);
            unsigned a2 = __float_as_uint(As[buf][(wm + lq    )*36 + kb + lr + 4]);
            unsigned a3 = __float_as_uint(As[buf][(wm + lq + 8)*36 + kb + lr + 4]);
            #pragma unroll
            for (int nf = 0; nf < 4; nf++) {
                unsigned b0 = __float_as_uint(Bs[buf][(kb + lr    )*72 + wn + nf*8 + lq]);
                unsigned b1 = __float_as_uint(Bs[buf][(kb + lr + 4)*72 + wn + nf*8 + lq]);
                asm volatile(
                    "mma.sync.aligned.m16n8k8.row.col.f32.tf32.tf32.f32 "
                    "{%0,%1,%2,%3}, {%4,%5,%6,%7}, {%8,%9}, {%0,%1,%2,%3};"
                    : "+f"(acc[nf][0]), "+f"(acc[nf][1]),
                      "+f"(acc[nf][2]), "+f"(acc[nf][3])
                    : "r"(a0), "r"(a1), "r"(a2), "r"(a3), "r"(b0), "r"(b1));
            }
        }
        __syncthreads();
    }

    // Epilogue: lane-pair exchange -> each lane holds (i,f,g,o) for one (row, unit)
    int r0 = m0 + wm + lq;
    bool ev = (lane & 1) == 0;
    #pragma unroll
    for (int nf = 0; nf < 4; nf++) {
        float p0 = __shfl_xor_sync(0xffffffffu, acc[nf][0], 1);
        float p1 = __shfl_xor_sync(0xffffffffu, acc[nf][1], 1);
        float p2 = __shfl_xor_sync(0xffffffffu, acc[nf][2], 1);
        float p3 = __shfl_xor_sync(0xffffffffu, acc[nf][3], 1);
        int u = (n0 + wn + nf*8) >> 2; u += (lr >> 1);
        int row = ev ? r0 : (r0 + 8);
        float iv, fv, gv, ov;
        if (ev) { iv = acc[nf][0]; fv = acc[nf][1]; gv = p0;         ov = p1;         }
        else    { iv = p2;         fv = p3;         gv = acc[nf][2]; ov = acc[nf][3]; }
        float4 bz = *(const float4*)&g_bias2[u*4];
        iv += bz.x; fv += bz.y; gv += bz.z; ov += bz.w;
        float co = g_c[row*512 + u];
        float cn = sigm(fv)*co + sigm(iv)*tanhf(gv);
        float hn = sigm(ov)*tanhf(cn);
        g_c[row*512 + u]          = cn;
        hnext[row*512 + u]        = hn;
        actn[row*KPM + 517 + u]   = to_tf32(hn);
    }
}

// ---------------- per-step fused: gem(t+1) [blocks 0..255] + head(t) [blocks 256..383] ---
__global__ void head_gem_kernel(const float* __restrict__ bfc, float* __restrict__ out,
                                const float* __restrict__ bconvh,
                                const float* __restrict__ Wp, int t)
{
    __shared__ float sbuf[8192];             // gem: h(4096)+w(4096); head: aliased
    int tid = threadIdx.x;                   // 256
    const float* hn = g_hbuf[(t + 1) & 1];

    if (blockIdx.x < 256) {                  // ---- gem for step t+1 ----
        gem_block(hn, bconvh, sbuf, blockIdx.x, tid);
        return;
    }

    // ---- head for 2 batches ----
    float* sh_h2  = sbuf;                    // 2*512
    float* sh_y   = sbuf + 1024;             // 2*128
    float* sh_mx  = sbuf + 1280;             // 2
    float* sh_inv = sbuf + 1282;             // 2
    int bs = tid >> 7;                       // batch slot 0/1
    int lt = tid & 127;
    int b = (blockIdx.x - 256)*2 + bs;

    for (int i = lt; i < 512; i += 128) sh_h2[bs*512 + i] = hn[b*512 + i];
    __syncthreads();

    float a = 0.f;
    if (lt < 123) {                          // row-contiguous Wp stream, MLP-rich
        const float4* wr = (const float4*)&Wp[lt*512];
        const float4* hv = (const float4*)&sh_h2[bs*512];
        #pragma unroll 8
        for (int i = 0; i < 128; i++) {
            float4 w = wr[i], h = hv[i];
            a += w.x*h.x + w.y*h.y + w.z*h.z + w.w*h.w;
        }
    }
    float y = a + ((lt < 123) ? bfc[lt] : 0.f);
    sh_y[bs*128 + lt] = y;
    __syncthreads();

    if (lt < 32) {                           // pi softmax stats over y[3..23)
        float v = (lt >= 3 && lt < 23) ? sh_y[bs*128 + lt] : -1e30f;
        float m = v;
        #pragma unroll
        for (int o = 16; o; o >>= 1) m = fmaxf(m, __shfl_xor_sync(0xffffffffu, m, o));
        float e = (lt >= 3 && lt < 23) ? expf(v - m) : 0.f;
        float s = e;
        #pragma unroll
        for (int o = 16; o; o >>= 1) s += __shfl_xor_sync(0xffffffffu, s, o);
        if (lt == 0) { sh_mx[bs] = m; sh_inv[bs] = 1.f / s; }
    }
    __syncthreads();

    if (lt < 123) {
        int row = b*257 + t;
        if (lt < 3)        out[6*OFF + row*3 + lt] = y;                           // pen logits
        else if (lt < 23)  out[          row*20 + (lt-3)]   = expf(y - sh_mx[bs]) * sh_inv[bs];
        else if (lt < 43)  out[1*OFF +  row*20 + (lt-23)]  = y;                   // mu1
        else if (lt < 63)  out[2*OFF +  row*20 + (lt-43)]  = y;                   // mu2
        else if (lt < 83)  out[3*OFF +  row*20 + (lt-63)]  = expf(y);             // s1
        else if (lt < 103) out[4*OFF +  row*20 + (lt-83)]  = expf(y);             // s2
        else               out[5*OFF +  row*20 + (lt-103)] = tanhf(y);            // corr
    }
}

// ---------------- launcher ----------------
extern "C" void kernel_launch(void* const* d_in, const int* in_sizes, int n_in,
                              void* d_out, int out_size)
{
    const float* backbone = (const float*)d_in[0];
    const float* z        = (const float*)d_in[1];
    const float* sketch   = (const float*)d_in[2];
    const float* Whc      = (const float*)d_in[3];
    const float* bhc      = (const float*)d_in[4];
    const float* Wch      = (const float*)d_in[5];
    const float* bch      = (const float*)d_in[6];
    const float* Kconv    = (const float*)d_in[7];
    const float* bconvf   = (const float*)d_in[8];
    const float* Watt     = (const float*)d_in[9];
    const float* batt     = (const float*)d_in[10];
    const float* Wih      = (const float*)d_in[11];
    const float* Whh      = (const float*)d_in[12];
    const float* bih      = (const float*)d_in[13];
    const float* bhh      = (const float*)d_in[14];
    const float* Wp       = (const float*)d_in[15];
    const float* bfc      = (const float*)d_in[16];
    float* out = (float*)d_out;
    (void)in_sizes; (void)n_in; (void)out_size;

    pack_kernel<<<32768, 256>>>(Wih, Whh, Wch, Kconv, backbone, bih, bhh);
    init_hc_kernel<<<64, 256>>>(z, Whc, bhc);
    conv_kernel<<<dim3(256, 4), 256>>>(backbone, bconvf);
    gem0_kernel<<<256, 256>>>(bch);

    for (int t = 0; t < TT; t++) {
        attn_kernel<<<256, 256>>>(Watt, batt, sketch, t);
        gates_kernel<<<dim3(4, 32), 256>>>(t);
        head_gem_kernel<<<384, 256>>>(bfc, out, bch, Wp, t);
    }
}